// round 16
// baseline (speedup 1.0000x reference)
#include <cuda_runtime.h>
#include <cuda_fp16.h>
#include <cstdint>
#include <math.h>

#define Bn 128
#define Ln 400
#define Dn 1024
#define Cn 256

// Activation planes, layout [L, B, C]: fp16 hi + s8 quant of hi + s8 quant of lo.
__device__ __half  g_Ahi[(size_t)Bn * Ln * Cn];
__device__ int8_t  g_Ah8[(size_t)Bn * Ln * Cn];
__device__ int8_t  g_Al8[(size_t)Bn * Ln * Cn];
__device__ __half  g_Bhi[(size_t)Bn * Ln * Cn];
__device__ int8_t  g_Bh8[(size_t)Bn * Ln * Cn];
__device__ int8_t  g_Bl8[(size_t)Bn * Ln * Cn];
// Split embeddings [B*L, D]
__device__ __half  g_Ehi[(size_t)Bn * Ln * Dn];
__device__ int8_t  g_Eh8[(size_t)Bn * Ln * Dn];
__device__ int8_t  g_El8[(size_t)Bn * Ln * Dn];
// Weights: conv [layer][tap][o][i], proj [o][k]
__device__ __half  g_wkhi[3 * 3 * Cn * Cn];
__device__ int8_t  g_wkh8[3 * 3 * Cn * Cn];
__device__ int8_t  g_wkl8[3 * 3 * Cn * Cn];
__device__ __half  g_wlhi[(size_t)Cn * Dn];
__device__ int8_t  g_wlh8[(size_t)Cn * Dn];
__device__ int8_t  g_wll8[(size_t)Cn * Dn];

// Quant scales (powers of 2): act hi 2^-3 (range +-16), act lo 2^-13,
// weight hi 2^-9 (range +-0.25), weight lo 2^-19. Both int8 products share
// scale 2^-13*2^-9 == 2^-3*2^-19 == 2^-22.
#define SA_INV   8.0f
#define SALO_INV 8192.0f
#define SB_INV   512.0f
#define SBLO_INV 524288.0f
#define SALO     (1.0f / 8192.0f)
#define CORR_SCALE 2.384185791015625e-07f   // 2^-22

// fp16 rows: 80 B stride (ldsm banks r*20 mod 32 distinct).
// int8 rows: 48 B stride (LDS.32 banks 12r+c4 mod 32 distinct).
#define RSTR 80
#define RS8  48
#define PF (128 * RSTR)               // fp16 plane 10240 B
#define P8 (128 * RS8)                // int8 plane 6144 B
// stage: A_h | B_h | A8h | A8l | B8h | B8l
#define STAGE (2 * PF + 4 * P8)       // 45056 B
#define NSTG 3
#define SMEM_TOT (NSTG * STAGE)       // 135168 B -> 1 CTA/SM

// ---------------- helpers ----------------
__device__ __forceinline__ uint32_t s2u(const void* p) {
    uint32_t a;
    asm("{ .reg .u64 t; cvta.to.shared.u64 t, %1; cvt.u32.u64 %0, t; }" : "=r"(a) : "l"(p));
    return a;
}
__device__ __forceinline__ void cpa16(uint32_t dst, const void* src) {
    asm volatile("cp.async.cg.shared.global [%0], [%1], 16;" :: "r"(dst), "l"(src) : "memory");
}
__device__ __forceinline__ void zfill16(uint32_t dst) {
    asm volatile("st.shared.v4.u32 [%0], {%1,%1,%1,%1};" :: "r"(dst), "r"(0u) : "memory");
}
__device__ __forceinline__ void cpa_commit() {
    asm volatile("cp.async.commit_group;" ::: "memory");
}
template <int N>
__device__ __forceinline__ void cpa_wait() {
    asm volatile("cp.async.wait_group %0;" :: "n"(N) : "memory");
}
__device__ __forceinline__ void ldsm4(uint32_t* r, uint32_t a) {
    asm volatile("ldmatrix.sync.aligned.m8n8.x4.shared.b16 {%0,%1,%2,%3}, [%4];"
                 : "=r"(r[0]), "=r"(r[1]), "=r"(r[2]), "=r"(r[3]) : "r"(a));
}
__device__ __forceinline__ uint32_t lds32(uint32_t a) {
    uint32_t v;
    asm volatile("ld.shared.b32 %0, [%1];" : "=r"(v) : "r"(a));
    return v;
}
__device__ __forceinline__ void mmaf32(float* d, const uint32_t* a, uint32_t b0, uint32_t b1) {
    asm volatile(
        "mma.sync.aligned.m16n8k16.row.col.f32.f16.f16.f32 "
        "{%0,%1,%2,%3}, {%4,%5,%6,%7}, {%8,%9}, {%0,%1,%2,%3};"
        : "+f"(d[0]), "+f"(d[1]), "+f"(d[2]), "+f"(d[3])
        : "r"(a[0]), "r"(a[1]), "r"(a[2]), "r"(a[3]), "r"(b0), "r"(b1));
}
__device__ __forceinline__ void mmai8(int* d, const uint32_t* a, uint32_t b0, uint32_t b1) {
    asm volatile(
        "mma.sync.aligned.m16n8k32.row.col.s32.s8.s8.s32 "
        "{%0,%1,%2,%3}, {%4,%5,%6,%7}, {%8,%9}, {%0,%1,%2,%3};"
        : "+r"(d[0]), "+r"(d[1]), "+r"(d[2]), "+r"(d[3])
        : "r"(a[0]), "r"(a[1]), "r"(a[2]), "r"(a[3]), "r"(b0), "r"(b1));
}
__device__ __forceinline__ int8_t q8(float v, float sinv) {
    int t = __float2int_rn(v * sinv);
    t = t < -127 ? -127 : (t > 127 ? 127 : t);
    return (int8_t)t;
}
// Split y into hi fp16 + quantized planes; write all three.
__device__ __forceinline__ void store3(float v0, float v1, __half* hi,
                                       int8_t* h8, int8_t* l8) {
    __half a = __float2half_rn(v0), b = __float2half_rn(v1);
    *(__half2*)hi = __halves2half2(a, b);
    float r0 = v0 - __half2float(a), r1 = v1 - __half2float(b);
    char2 ch = make_char2(q8(__half2float(a), SA_INV), q8(__half2float(b), SA_INV));
    char2 cl = make_char2(q8(r0, SALO_INV), q8(r1, SALO_INV));
    *(char2*)h8 = ch;
    *(char2*)l8 = cl;
}

// ---------------------------------------------------------------------------
// Weight prep: conv w[o][i][k] -> [(tap*256+o)*256+i]; proj Wl[k][o] -> [o*1024+k]
// ---------------------------------------------------------------------------
__global__ void wprep_all_kernel(const float* __restrict__ w0,
                                 const float* __restrict__ w1,
                                 const float* __restrict__ w2,
                                 const float* __restrict__ wl,
                                 __half* __restrict__ wkh, int8_t* __restrict__ wk8,
                                 int8_t* __restrict__ wkl8,
                                 __half* __restrict__ wlh, int8_t* __restrict__ wl8h,
                                 int8_t* __restrict__ wl8l) {
    const int bid = blockIdx.x;
    if (bid < 2304) {
        const int layer = bid / 768, blk = bid - layer * 768;
        const float* w = (layer == 0) ? w0 : (layer == 1) ? w1 : w2;
        const int idx = blk * 256 + threadIdx.x;
        const int o = idx / (Cn * 3);
        const int rem = idx - o * (Cn * 3);
        const int i = rem / 3, k = rem - i * 3;
        const float v = w[idx];
        const __half h = __float2half_rn(v);
        const size_t d = (size_t)layer * 3 * Cn * Cn + ((size_t)k * Cn + o) * Cn + i;
        wkh[d] = h;
        wk8[d] = q8(__half2float(h), SB_INV);
        wkl8[d] = q8(v - __half2float(h), SBLO_INV);
    } else {
        const int idx = (bid - 2304) * 256 + threadIdx.x;
        const int o = idx >> 10, k = idx & 1023;
        const float v = wl[(size_t)k * Cn + o];
        const __half h = __float2half_rn(v);
        wlh[idx] = h;
        wl8h[idx] = q8(__half2float(h), SB_INV);
        wl8l[idx] = q8(v - __half2float(h), SBLO_INV);
    }
}
__global__ void esplit_kernel(const float4* __restrict__ E,
                              __half2* __restrict__ hi,
                              int8_t* __restrict__ h8, int8_t* __restrict__ l8) {
    size_t idx = (size_t)blockIdx.x * 256 + threadIdx.x;
    float4 v = E[idx];
    __half a = __float2half_rn(v.x), b = __float2half_rn(v.y);
    __half c = __float2half_rn(v.z), d = __float2half_rn(v.w);
    hi[idx * 2]     = __halves2half2(a, b);
    hi[idx * 2 + 1] = __halves2half2(c, d);
    char4 ch = make_char4(q8(__half2float(a), SA_INV), q8(__half2float(b), SA_INV),
                          q8(__half2float(c), SA_INV), q8(__half2float(d), SA_INV));
    char4 cl = make_char4(q8(v.x - __half2float(a), SALO_INV),
                          q8(v.y - __half2float(b), SALO_INV),
                          q8(v.z - __half2float(c), SALO_INV),
                          q8(v.w - __half2float(d), SALO_INV));
    *(char4*)(h8 + idx * 4) = ch;
    *(char4*)(l8 + idx * 4) = cl;
}

// ---------------------------------------------------------------------------
// Mixed fp16+int8 mma GEMM/conv on [L,B,C]. CTA M128 x N128, 512 thr, 16
// warps 4m x 4n (warp tile M32 x N32). 3-stage cp.async pipeline.
// Per k32 chunk per warp: 16 fp16 MMA (Ahi*Bhi, f32 acc) + 16 int8 MMA
// (Alo8*Bhi8 + Ahi8*Blo8, shared s32 acc, scale 2^-22).
// Conv: 24 chunks (3 taps x 8). Proj: 32 chunks.
// ---------------------------------------------------------------------------
template <bool PROJ, int DIL, bool RELU, bool SPLIT>
__global__ void __launch_bounds__(512, 1) mma_kernel(
    const __half* __restrict__ Xhi, const int8_t* __restrict__ Xh8,
    const int8_t* __restrict__ Xl8,
    const __half* __restrict__ Whi, const int8_t* __restrict__ Wh8,
    const int8_t* __restrict__ Wl8,
    const float* __restrict__ bias,
    __half* __restrict__ Yhi, int8_t* __restrict__ Yh8, int8_t* __restrict__ Yl8,
    float* __restrict__ Yf) {
    constexpr int NCH = PROJ ? 32 : 24;

    extern __shared__ __align__(16) char smem[];
    const int tid = threadIdx.x, wid = tid >> 5, lane = tid & 31;
    const int r4 = lane >> 2, c4 = lane & 3;
    const int wm = (wid & 3) * 32, wn = ((wid >> 2) & 3) * 32;
    const uint32_t smem_u = s2u(smem);

    const int lane15 = lane & 15;
    const uint32_t a_off = ((lane >> 4) & 1) << 4;
    const int b_rowl = (lane & 7) + ((lane >> 4) & 1) * 8;
    const uint32_t b_off = ((lane >> 3) & 1) << 4;

    const int n0 = (blockIdx.x & 1) * 128;
    const int tile = blockIdx.x >> 1;      // proj: m-tile; conv: l index
    const int m0 = tile * 128;

    float acc[2][4][4];
    int   cacc[2][4][4];
#pragma unroll
    for (int mt = 0; mt < 2; mt++)
#pragma unroll
        for (int nt = 0; nt < 4; nt++)
#pragma unroll
            for (int j = 0; j < 4; j++) { acc[mt][nt][j] = 0.f; cacc[mt][nt][j] = 0; }

    auto load_chunk = [&](int c) {
        const uint32_t sb = smem_u + (c % NSTG) * STAGE;
        const int tap = PROJ ? 0 : (c >> 3);
        const int kc = PROJ ? c : (c & 7);
        const int lsrc = PROJ ? 0 : (tile + (tap - 1) * DIL);
        const bool avalid = PROJ || ((unsigned)lsrc < (unsigned)Ln);
        const int KD = PROJ ? Dn : Cn;
        // A fp16: 512 ops
        {
            const int row = tid >> 2, cg = tid & 3;
            const uint32_t dst = sb + row * RSTR + cg * 16;
            size_t srow = PROJ ? (size_t)(m0 + row) : ((size_t)lsrc * Bn + row);
            if (PROJ || avalid) cpa16(dst, Xhi + srow * KD + kc * 32 + cg * 8);
            else zfill16(dst);
        }
        // B fp16: 512 ops
        {
            const int row = tid >> 2, cg = tid & 3;
            const uint32_t dst = sb + PF + row * RSTR + cg * 16;
            size_t srow = PROJ ? (size_t)(n0 + row)
                               : ((size_t)tap * Cn + n0 + row);
            cpa16(dst, Whi + srow * KD + kc * 32 + cg * 8);
        }
        // A int8 (2 planes): 512 ops
        {
            const int plane = tid >> 8, row = (tid >> 1) & 127, cg = tid & 1;
            const uint32_t dst = sb + 2 * PF + plane * P8 + row * RS8 + cg * 16;
            const int8_t* P = plane ? Xl8 : Xh8;
            size_t srow = PROJ ? (size_t)(m0 + row) : ((size_t)lsrc * Bn + row);
            if (PROJ || avalid) cpa16(dst, P + srow * KD + kc * 32 + cg * 16);
            else zfill16(dst);
        }
        // B int8 (2 planes): 512 ops
        {
            const int plane = tid >> 8, row = (tid >> 1) & 127, cg = tid & 1;
            const uint32_t dst = sb + 2 * PF + (2 + plane) * P8 + row * RS8 + cg * 16;
            const int8_t* P = plane ? Wl8 : Wh8;
            size_t srow = PROJ ? (size_t)(n0 + row)
                               : ((size_t)tap * Cn + n0 + row);
            cpa16(dst, P + srow * KD + kc * 32 + cg * 16);
        }
        cpa_commit();
    };

    load_chunk(0);
    load_chunk(1);
    for (int c = 0; c < NCH; c++) {
        cpa_wait<1>();
        __syncthreads();
        if (c + 2 < NCH) load_chunk(c + 2);

        const uint32_t sb = smem_u + (c % NSTG) * STAGE;
        // ---- fp16 main sweep (Ahi x Bhi) ----
        const uint32_t ab = sb + (wm + lane15) * RSTR + a_off;
        const uint32_t bbs = sb + PF + (wn + b_rowl) * RSTR + b_off;
#pragma unroll
        for (int ks = 0; ks < 2; ks++) {
            uint32_t ah[2][4], bh[2][4];
            ldsm4(ah[0], ab + ks * 32);
            ldsm4(ah[1], ab + 16 * RSTR + ks * 32);
            ldsm4(bh[0], bbs + ks * 32);
            ldsm4(bh[1], bbs + 16 * RSTR + ks * 32);
#pragma unroll
            for (int p = 0; p < 2; p++)
#pragma unroll
                for (int h = 0; h < 2; h++) {
                    const int nt = 2 * p + h;
                    mmaf32(acc[0][nt], ah[0], bh[p][2 * h], bh[p][2 * h + 1]);
                    mmaf32(acc[1][nt], ah[1], bh[p][2 * h], bh[p][2 * h + 1]);
                }
        }
        // ---- int8 correction sweeps (k32 each) ----
        const uint32_t a8h = sb + 2 * PF;
        const uint32_t a8l = a8h + P8;
        const uint32_t b8h = a8h + 2 * P8;
        const uint32_t b8l = a8h + 3 * P8;
        {
            // sweep 2: Alo8 x Bhi8
            uint32_t af[2][4], bf[4][2];
#pragma unroll
            for (int mt = 0; mt < 2; mt++) {
                const uint32_t r0 = a8l + (wm + mt * 16 + r4) * RS8 + c4 * 4;
                af[mt][0] = lds32(r0);
                af[mt][1] = lds32(r0 + 8 * RS8);
                af[mt][2] = lds32(r0 + 16);
                af[mt][3] = lds32(r0 + 8 * RS8 + 16);
            }
#pragma unroll
            for (int nt = 0; nt < 4; nt++) {
                const uint32_t nb = b8h + (wn + nt * 8 + r4) * RS8 + c4 * 4;
                bf[nt][0] = lds32(nb);
                bf[nt][1] = lds32(nb + 16);
            }
#pragma unroll
            for (int nt = 0; nt < 4; nt++) {
                mmai8(cacc[0][nt], af[0], bf[nt][0], bf[nt][1]);
                mmai8(cacc[1][nt], af[1], bf[nt][0], bf[nt][1]);
            }
            // sweep 3: Ahi8 x Blo8 (reuse frag regs)
#pragma unroll
            for (int mt = 0; mt < 2; mt++) {
                const uint32_t r0 = a8h + (wm + mt * 16 + r4) * RS8 + c4 * 4;
                af[mt][0] = lds32(r0);
                af[mt][1] = lds32(r0 + 8 * RS8);
                af[mt][2] = lds32(r0 + 16);
                af[mt][3] = lds32(r0 + 8 * RS8 + 16);
            }
#pragma unroll
            for (int nt = 0; nt < 4; nt++) {
                const uint32_t nb = b8l + (wn + nt * 8 + r4) * RS8 + c4 * 4;
                bf[nt][0] = lds32(nb);
                bf[nt][1] = lds32(nb + 16);
            }
#pragma unroll
            for (int nt = 0; nt < 4; nt++) {
                mmai8(cacc[0][nt], af[0], bf[nt][0], bf[nt][1]);
                mmai8(cacc[1][nt], af[1], bf[nt][0], bf[nt][1]);
            }
        }
    }

    // ---- epilogue: merge corrections, bias (+ReLU); store planes / fp32 ----
#pragma unroll
    for (int mt = 0; mt < 2; mt++) {
        const int rowl = wm + mt * 16 + r4;
#pragma unroll
        for (int half = 0; half < 2; half++) {
            const int rl = rowl + half * 8;
            size_t yrow;
            if (PROJ) {
                const int m = m0 + rl;
                const int b = m / Ln, l = m - b * Ln;
                yrow = (size_t)l * Bn + b;
            } else if (SPLIT) {
                yrow = (size_t)tile * Bn + rl;
            } else {
                yrow = (size_t)rl * Ln + tile;
            }
#pragma unroll
            for (int nt = 0; nt < 4; nt++) {
                const int col = wn + nt * 8 + c4 * 2;
                const float bz0 = __ldg(bias + n0 + col);
                const float bz1 = __ldg(bias + n0 + col + 1);
                float v0 = acc[mt][nt][2 * half]
                         + (float)cacc[mt][nt][2 * half] * CORR_SCALE + bz0;
                float v1 = acc[mt][nt][2 * half + 1]
                         + (float)cacc[mt][nt][2 * half + 1] * CORR_SCALE + bz1;
                if (RELU) { v0 = fmaxf(v0, 0.f); v1 = fmaxf(v1, 0.f); }
                if (SPLIT) {
                    const size_t o = yrow * Cn + n0 + col;
                    store3(v0, v1, Yhi + o, Yh8 + o, Yl8 + o);
                } else {
                    *(float2*)(Yf + yrow * Cn + n0 + col) = make_float2(v0, v1);
                }
            }
        }
    }
}

// ---------------------------------------------------------------------------
// LayerNorm over L per (b,c) on [L,B,C] planes (x = hi + lo8*2^-13), 2-pass.
// Block 256 thr = 64 channels x 4 L-strips. Grid (Bn, 4).
// torch-style: unbiased var (ddof=1), divide by (std + eps).
// ---------------------------------------------------------------------------
template <bool RELU>
__global__ __launch_bounds__(256) void ln_kernel(
    __half* __restrict__ hi, int8_t* __restrict__ h8, int8_t* __restrict__ l8,
    const float* __restrict__ g, const float* __restrict__ be) {
    __shared__ float red[2][4][64];
    __shared__ float stat[2][64];
    const int b = blockIdx.x, cg = blockIdx.y;
    const int cl = threadIdx.x & 63, strip = threadIdx.x >> 6;
    const size_t base = (size_t)b * Cn + cg * 64 + cl;

    float s = 0.f, q = 0.f;
    for (int l = strip; l < Ln; l += 4) {
        const size_t off = base + (size_t)l * Bn * Cn;
        float x = __half2float(hi[off]) + (float)l8[off] * SALO;
        if (RELU) x = fmaxf(x, 0.f);
        s += x; q += x * x;
    }
    red[0][strip][cl] = s;
    red[1][strip][cl] = q;
    __syncthreads();
    if (threadIdx.x < 64) {
        float st = red[0][0][cl] + red[0][1][cl] + red[0][2][cl] + red[0][3][cl];
        float qt = red[1][0][cl] + red[1][1][cl] + red[1][2][cl] + red[1][3][cl];
        const float mean = st * (1.f / Ln);
        const float var = fmaxf((qt - st * mean) * (1.f / (Ln - 1)), 0.f);
        stat[0][cl] = mean;
        stat[1][cl] = 1.f / (sqrtf(var) + 1e-6f);
    }
    __syncthreads();
    const float mean = stat[0][cl], inv = stat[1][cl];
    for (int l = strip; l < Ln; l += 4) {
        const size_t off = base + (size_t)l * Bn * Cn;
        float x = __half2float(hi[off]) + (float)l8[off] * SALO;
        if (RELU) x = fmaxf(x, 0.f);
        const float y = g[l] * ((x - mean) * inv) + be[l];
        const __half h = __float2half_rn(y);
        hi[off] = h;
        h8[off] = q8(__half2float(h), SA_INV);
        l8[off] = q8(y - __half2float(h), SALO_INV);
    }
}

// ---------------------------------------------------------------------------
// Host orchestration
// ---------------------------------------------------------------------------
extern "C" void kernel_launch(void* const* d_in, const int* in_sizes, int n_in,
                              void* d_out, int out_size) {
    const float* E   = (const float*)d_in[0];
    const float* Wl  = (const float*)d_in[2];
    const float* bl  = (const float*)d_in[3];
    const float* w0  = (const float*)d_in[4];
    const float* b0  = (const float*)d_in[5];
    const float* w1  = (const float*)d_in[6];
    const float* b1  = (const float*)d_in[7];
    const float* w2  = (const float*)d_in[8];
    const float* b2  = (const float*)d_in[9];
    const float* g1  = (const float*)d_in[10];
    const float* be1 = (const float*)d_in[11];
    const float* g2  = (const float*)d_in[12];
    const float* be2 = (const float*)d_in[13];
    float* out = (float*)d_out;

    __half *Ahp, *Bhp, *Ehp, *wkh, *wlh;
    int8_t *Ah8, *Al8, *Bh8, *Bl8, *Eh8, *El8, *wk8, *wkl8, *wl8h, *wl8l;
    cudaGetSymbolAddress((void**)&Ahp, g_Ahi);
    cudaGetSymbolAddress((void**)&Ah8, g_Ah8);
    cudaGetSymbolAddress((void**)&Al8, g_Al8);
    cudaGetSymbolAddress((void**)&Bhp, g_Bhi);
    cudaGetSymbolAddress((void**)&Bh8, g_Bh8);
    cudaGetSymbolAddress((void**)&Bl8, g_Bl8);
    cudaGetSymbolAddress((void**)&Ehp, g_Ehi);
    cudaGetSymbolAddress((void**)&Eh8, g_Eh8);
    cudaGetSymbolAddress((void**)&El8, g_El8);
    cudaGetSymbolAddress((void**)&wkh, g_wkhi);
    cudaGetSymbolAddress((void**)&wk8, g_wkh8);
    cudaGetSymbolAddress((void**)&wkl8, g_wkl8);
    cudaGetSymbolAddress((void**)&wlh, g_wlhi);
    cudaGetSymbolAddress((void**)&wl8h, g_wlh8);
    cudaGetSymbolAddress((void**)&wl8l, g_wll8);
    __half* wk0h = wkh;               int8_t* wk0a = wk8;               int8_t* wk0b = wkl8;
    __half* wk1h = wkh + 3 * Cn * Cn; int8_t* wk1a = wk8 + 3 * Cn * Cn; int8_t* wk1b = wkl8 + 3 * Cn * Cn;
    __half* wk2h = wkh + 6 * Cn * Cn; int8_t* wk2a = wk8 + 6 * Cn * Cn; int8_t* wk2b = wkl8 + 6 * Cn * Cn;

    cudaFuncSetAttribute(mma_kernel<true, 1, false, true>,
                         cudaFuncAttributeMaxDynamicSharedMemorySize, SMEM_TOT);
    cudaFuncSetAttribute(mma_kernel<false, 1, true, true>,
                         cudaFuncAttributeMaxDynamicSharedMemorySize, SMEM_TOT);
    cudaFuncSetAttribute(mma_kernel<false, 1, false, true>,
                         cudaFuncAttributeMaxDynamicSharedMemorySize, SMEM_TOT);
    cudaFuncSetAttribute(mma_kernel<false, 2, false, true>,
                         cudaFuncAttributeMaxDynamicSharedMemorySize, SMEM_TOT);
    cudaFuncSetAttribute(mma_kernel<false, 2, false, false>,
                         cudaFuncAttributeMaxDynamicSharedMemorySize, SMEM_TOT);

    wprep_all_kernel<<<3328, 256>>>(w0, w1, w2, Wl, wkh, wk8, wkl8, wlh, wl8h, wl8l);
    esplit_kernel<<<51200, 256>>>((const float4*)E, (__half2*)Ehp, Eh8, El8);

    // projection -> A planes [L,B,C]
    mma_kernel<true, 1, false, true><<<800, 512, SMEM_TOT>>>(
        Ehp, Eh8, El8, wlh, wl8h, wl8l, bl, Ahp, Ah8, Al8, nullptr);

    const int CG = Ln * 2;
    const dim3 LG(Bn, 4);

    // net 1: A -> B
    mma_kernel<false, 1, true,  true><<<CG, 512, SMEM_TOT>>>(Ahp, Ah8, Al8, wk0h, wk0a, wk0b, b0, Bhp, Bh8, Bl8, nullptr);
    ln_kernel<false><<<LG, 256>>>(Bhp, Bh8, Bl8, g1, be1);
    mma_kernel<false, 1, false, true><<<CG, 512, SMEM_TOT>>>(Bhp, Bh8, Bl8, wk1h, wk1a, wk1b, b1, Ahp, Ah8, Al8, nullptr);
    mma_kernel<false, 2, false, true><<<CG, 512, SMEM_TOT>>>(Ahp, Ah8, Al8, wk2h, wk2a, wk2b, b2, Bhp, Bh8, Bl8, nullptr);

    ln_kernel<true><<<LG, 256>>>(Bhp, Bh8, Bl8, g2, be2);   // ReLU + outer LN

    // net 2: B -> A
    mma_kernel<false, 1, true,  true><<<CG, 512, SMEM_TOT>>>(Bhp, Bh8, Bl8, wk0h, wk0a, wk0b, b0, Ahp, Ah8, Al8, nullptr);
    ln_kernel<false><<<LG, 256>>>(Ahp, Ah8, Al8, g1, be1);
    mma_kernel<false, 1, false, true><<<CG, 512, SMEM_TOT>>>(Ahp, Ah8, Al8, wk1h, wk1a, wk1b, b1, Bhp, Bh8, Bl8, nullptr);
    mma_kernel<false, 2, false, true><<<CG, 512, SMEM_TOT>>>(Bhp, Bh8, Bl8, wk2h, wk2a, wk2b, b2, Ahp, Ah8, Al8, nullptr);

    // net 3: A -> B
    mma_kernel<false, 1, true,  true><<<CG, 512, SMEM_TOT>>>(Ahp, Ah8, Al8, wk0h, wk0a, wk0b, b0, Bhp, Bh8, Bl8, nullptr);
    ln_kernel<false><<<LG, 256>>>(Bhp, Bh8, Bl8, g1, be1);
    mma_kernel<false, 1, false, true><<<CG, 512, SMEM_TOT>>>(Bhp, Bh8, Bl8, wk1h, wk1a, wk1b, b1, Ahp, Ah8, Al8, nullptr);
    mma_kernel<false, 2, false, true><<<CG, 512, SMEM_TOT>>>(Ahp, Ah8, Al8, wk2h, wk2a, wk2b, b2, Bhp, Bh8, Bl8, nullptr);

    // net 4: B -> out (final conv writes fp32 d_out [B,L,C])
    mma_kernel<false, 1, true,  true><<<CG, 512, SMEM_TOT>>>(Bhp, Bh8, Bl8, wk0h, wk0a, wk0b, b0, Ahp, Ah8, Al8, nullptr);
    ln_kernel<false><<<LG, 256>>>(Ahp, Ah8, Al8, g1, be1);
    mma_kernel<false, 1, false, true><<<CG, 512, SMEM_TOT>>>(Ahp, Ah8, Al8, wk1h, wk1a, wk1b, b1, Bhp, Bh8, Bl8, nullptr);
    mma_kernel<false, 2, false, false><<<CG, 512, SMEM_TOT>>>(Bhp, Bh8, Bl8, wk2h, wk2a, wk2b, b2, nullptr, nullptr, nullptr, out);
}

// round 17
// speedup vs baseline: 2.4437x; 2.4437x over previous
#include <cuda_runtime.h>
#include <cuda_fp16.h>
#include <cstdint>
#include <math.h>

#define Bn 128
#define Ln 400
#define Dn 1024
#define Cn 256

// Activation ping-pong planes (fp16 hi/lo), layout [L, B, C]
__device__ __half g_Ahi[(size_t)Bn * Ln * Cn];
__device__ __half g_Alo[(size_t)Bn * Ln * Cn];
__device__ __half g_Bhi[(size_t)Bn * Ln * Cn];
__device__ __half g_Blo[(size_t)Bn * Ln * Cn];
// Split embeddings [B*L, D]
__device__ __half g_Ehi[(size_t)Bn * Ln * Dn];
__device__ __half g_Elo[(size_t)Bn * Ln * Dn];
// Split weights: conv [layer][tap][o][i], proj [o][k]
__device__ __half g_wkhi[3 * 3 * Cn * Cn];
__device__ __half g_wklo[3 * 3 * Cn * Cn];
__device__ __half g_wlhi[(size_t)Cn * Dn];
__device__ __half g_wllo[(size_t)Cn * Dn];

// Row stride 80 B (40 fp16): ldmatrix 8-row phases hit banks r*20 mod 32
// (all distinct), 16B-aligned for cp.async.
#define RSTR 80
#define PL (128 * RSTR)          // one plane tile: 10240 B
#define STAGE (4 * PL)           // Ahi,Alo,Bhi,Blo: 40960 B
#define SMEM_TOT (2 * STAGE)     // 2 stages: 81920 B -> 2 CTAs/SM
#define SMEM_LN (400 * 64 * 2 * 2)   // LN slab: hi+lo, 102400 B

// ---------------- helpers ----------------
__device__ __forceinline__ uint32_t s2u(const void* p) {
    uint32_t a;
    asm("{ .reg .u64 t; cvta.to.shared.u64 t, %1; cvt.u32.u64 %0, t; }" : "=r"(a) : "l"(p));
    return a;
}
__device__ __forceinline__ void cpa16(uint32_t dst, const void* src) {
    asm volatile("cp.async.cg.shared.global [%0], [%1], 16;" :: "r"(dst), "l"(src) : "memory");
}
__device__ __forceinline__ void zfill16(uint32_t dst) {
    asm volatile("st.shared.v4.u32 [%0], {%1,%1,%1,%1};" :: "r"(dst), "r"(0u) : "memory");
}
__device__ __forceinline__ void cpa_commit() {
    asm volatile("cp.async.commit_group;" ::: "memory");
}
template <int N>
__device__ __forceinline__ void cpa_wait() {
    asm volatile("cp.async.wait_group %0;" :: "n"(N) : "memory");
}
__device__ __forceinline__ void ldsm4(uint32_t* r, uint32_t a) {
    asm volatile("ldmatrix.sync.aligned.m8n8.x4.shared.b16 {%0,%1,%2,%3}, [%4];"
                 : "=r"(r[0]), "=r"(r[1]), "=r"(r[2]), "=r"(r[3]) : "r"(a));
}
__device__ __forceinline__ void mmaf32(float* d, const uint32_t* a, uint32_t b0, uint32_t b1) {
    asm volatile(
        "mma.sync.aligned.m16n8k16.row.col.f32.f16.f16.f32 "
        "{%0,%1,%2,%3}, {%4,%5,%6,%7}, {%8,%9}, {%0,%1,%2,%3};"
        : "+f"(d[0]), "+f"(d[1]), "+f"(d[2]), "+f"(d[3])
        : "r"(a[0]), "r"(a[1]), "r"(a[2]), "r"(a[3]), "r"(b0), "r"(b1));
}
__device__ __forceinline__ void split2(float v0, float v1,
                                       __half2* hi, __half2* lo) {
    __half h0 = __float2half_rn(v0), h1 = __float2half_rn(v1);
    *hi = __halves2half2(h0, h1);
    *lo = __halves2half2(__float2half_rn(v0 - __half2float(h0)),
                         __float2half_rn(v1 - __half2float(h1)));
}

// ---------------------------------------------------------------------------
// Prep: all weights in ONE kernel; embeddings split in another.
// conv: w[o][i][k] -> [(tap*256+o)*256 + i];  proj: Wl[k][o] -> [o*1024+k]
// ---------------------------------------------------------------------------
__global__ void wprep_all_kernel(const float* __restrict__ w0,
                                 const float* __restrict__ w1,
                                 const float* __restrict__ w2,
                                 const float* __restrict__ wl,
                                 __half* __restrict__ wkh,
                                 __half* __restrict__ wkl,
                                 __half* __restrict__ wlh,
                                 __half* __restrict__ wll) {
    const int bid = blockIdx.x;
    if (bid < 2304) {
        const int layer = bid / 768, blk = bid - layer * 768;
        const float* w = (layer == 0) ? w0 : (layer == 1) ? w1 : w2;
        const int idx = blk * 256 + threadIdx.x;            // 0..196607
        const int o = idx / (Cn * 3);
        const int rem = idx - o * (Cn * 3);
        const int i = rem / 3, k = rem - i * 3;
        const float v = w[idx];
        const __half h = __float2half_rn(v);
        const size_t d = (size_t)layer * 3 * Cn * Cn + ((size_t)k * Cn + o) * Cn + i;
        wkh[d] = h;
        wkl[d] = __float2half_rn(v - __half2float(h));
    } else {
        const int idx = (bid - 2304) * 256 + threadIdx.x;   // 0..262143
        const int o = idx >> 10, k = idx & 1023;
        const float v = wl[(size_t)k * Cn + o];
        const __half h = __float2half_rn(v);
        wlh[idx] = h;
        wll[idx] = __float2half_rn(v - __half2float(h));
    }
}
__global__ void esplit_kernel(const float4* __restrict__ E,
                              __half2* __restrict__ hi,
                              __half2* __restrict__ lo) {
    size_t idx = (size_t)blockIdx.x * 256 + threadIdx.x;
    float4 v = E[idx];
    split2(v.x, v.y, &hi[idx * 2], &lo[idx * 2]);
    split2(v.z, v.w, &hi[idx * 2 + 1], &lo[idx * 2 + 1]);
}

// ---------------------------------------------------------------------------
// fp16x3 mma GEMM/conv on [L,B,C] (R11 structure: fastest measured).
// CTA M128 x N128-half, 256 thr, 8 warps (wm=(wid&3)*32, wn=(wid>>2)*64).
// 2-stage cp.async, single sync per chunk: wait(c) -> sync -> load(c+1) ->
// compute(c). 3 f32-acc sweeps per k-step (hh, lh, hl).
// Conv: 24 k-chunks (3 taps x 8). Proj: 32 chunks.
// ---------------------------------------------------------------------------
template <bool PROJ, int DIL, bool RELU, bool SPLIT>
__global__ void __launch_bounds__(256, 2) mma_kernel(
    const __half* __restrict__ Xhi, const __half* __restrict__ Xlo,
    const __half* __restrict__ Whi, const __half* __restrict__ Wlo,
    const float* __restrict__ bias,
    __half* __restrict__ Yhi, __half* __restrict__ Ylo,
    float* __restrict__ Yf) {
    constexpr int NCH = PROJ ? 32 : 24;

    extern __shared__ __align__(16) char smem[];
    const int tid = threadIdx.x, wid = tid >> 5, lane = tid & 31;
    const int r4 = lane >> 2, c4 = lane & 3;
    const int wm = (wid & 3) * 32, wn = (wid >> 2) * 64;
    const uint32_t smem_u = s2u(smem);

    // ldmatrix per-lane address components
    const int lane15 = lane & 15;
    const uint32_t a_off = ((lane >> 4) & 1) << 4;
    const int b_rowl = (lane & 7) + ((lane >> 4) & 1) * 8;
    const uint32_t b_off = ((lane >> 3) & 1) << 4;

    const int n0 = (blockIdx.x & 1) * 128;
    const int tile = blockIdx.x >> 1;      // proj: m-tile; conv: l index
    const int m0 = tile * 128;

    float acc[2][8][4];
#pragma unroll
    for (int mt = 0; mt < 2; mt++)
#pragma unroll
        for (int nt = 0; nt < 8; nt++)
#pragma unroll
            for (int j = 0; j < 4; j++) acc[mt][nt][j] = 0.f;

    auto load_chunk = [&](int c) {
        const uint32_t sb = smem_u + (c & 1) * STAGE;
        const int tap = PROJ ? 0 : (c >> 3);
        const int kc = PROJ ? c : (c & 7);
        const int lsrc = PROJ ? 0 : (tile + (tap - 1) * DIL);
        const bool avalid = PROJ || ((unsigned)lsrc < (unsigned)Ln);
#pragma unroll
        for (int q = 0; q < 4; q++) {                       // A planes: 1024 ops
            const int idx = q * 256 + tid;
            const int plane = idx >> 9, row = (idx >> 2) & 127, cg = idx & 3;
            const uint32_t dst = sb + plane * PL + row * RSTR + cg * 16;
            const __half* P = plane ? Xlo : Xhi;
            if (PROJ)
                cpa16(dst, P + (size_t)(m0 + row) * Dn + kc * 32 + cg * 8);
            else if (avalid)
                cpa16(dst, P + ((size_t)lsrc * Bn + row) * Cn + kc * 32 + cg * 8);
            else
                zfill16(dst);
        }
#pragma unroll
        for (int q = 0; q < 4; q++) {                       // B planes: 1024 ops
            const int idx = q * 256 + tid;
            const int plane = idx >> 9, row = (idx >> 2) & 127, cg = idx & 3;
            const uint32_t dst = sb + (2 + plane) * PL + row * RSTR + cg * 16;
            const __half* P = plane ? Wlo : Whi;
            if (PROJ)
                cpa16(dst, P + (size_t)(n0 + row) * Dn + kc * 32 + cg * 8);
            else
                cpa16(dst, P + ((size_t)tap * Cn + n0 + row) * Cn + kc * 32 + cg * 8);
        }
        cpa_commit();
    };

    load_chunk(0);
    for (int c = 0; c < NCH; c++) {
        cpa_wait<0>();          // my copies for stage c done
        __syncthreads();        // all threads past compute(c-1); stage c visible
        if (c + 1 < NCH) load_chunk(c + 1);

        const uint32_t sb = smem_u + (c & 1) * STAGE;
        const uint32_t ab = sb + (wm + lane15) * RSTR + a_off;
        const uint32_t bbs = sb + 2 * PL + (wn + b_rowl) * RSTR + b_off;
#pragma unroll
        for (int ks = 0; ks < 2; ks++) {
            uint32_t ah[2][4], al[2][4], bh[4][4], bl[4][4];
            ldsm4(ah[0], ab + ks * 32);
            ldsm4(ah[1], ab + 16 * RSTR + ks * 32);
            ldsm4(al[0], ab + PL + ks * 32);
            ldsm4(al[1], ab + PL + 16 * RSTR + ks * 32);
#pragma unroll
            for (int p = 0; p < 4; p++) {
                ldsm4(bh[p], bbs + p * 16 * RSTR + ks * 32);
                ldsm4(bl[p], bbs + PL + p * 16 * RSTR + ks * 32);
            }
            // Sweep 1: Ahi x Bhi
#pragma unroll
            for (int p = 0; p < 4; p++)
#pragma unroll
                for (int h = 0; h < 2; h++) {
                    const int nt = 2 * p + h;
                    mmaf32(acc[0][nt], ah[0], bh[p][2 * h], bh[p][2 * h + 1]);
                    mmaf32(acc[1][nt], ah[1], bh[p][2 * h], bh[p][2 * h + 1]);
                }
            // Sweep 2: Alo x Bhi
#pragma unroll
            for (int p = 0; p < 4; p++)
#pragma unroll
                for (int h = 0; h < 2; h++) {
                    const int nt = 2 * p + h;
                    mmaf32(acc[0][nt], al[0], bh[p][2 * h], bh[p][2 * h + 1]);
                    mmaf32(acc[1][nt], al[1], bh[p][2 * h], bh[p][2 * h + 1]);
                }
            // Sweep 3: Ahi x Blo
#pragma unroll
            for (int p = 0; p < 4; p++)
#pragma unroll
                for (int h = 0; h < 2; h++) {
                    const int nt = 2 * p + h;
                    mmaf32(acc[0][nt], ah[0], bl[p][2 * h], bl[p][2 * h + 1]);
                    mmaf32(acc[1][nt], ah[1], bl[p][2 * h], bl[p][2 * h + 1]);
                }
        }
    }

    // ---- epilogue: bias (+ReLU); split-store to [L,B,C] or fp32 [B,L,C] ----
#pragma unroll
    for (int mt = 0; mt < 2; mt++) {
        const int rowl = wm + mt * 16 + r4;    // local m row (conv: batch b)
#pragma unroll
        for (int half = 0; half < 2; half++) {
            const int rl = rowl + half * 8;
            size_t yrow;
            if (PROJ) {
                const int m = m0 + rl;
                const int b = m / Ln, l = m - b * Ln;
                yrow = (size_t)l * Bn + b;
            } else if (SPLIT) {
                yrow = (size_t)tile * Bn + rl;           // [L,B,C]
            } else {
                yrow = (size_t)rl * Ln + tile;           // fp32 out [B,L,C]
            }
#pragma unroll
            for (int nt = 0; nt < 8; nt++) {
                const int col = wn + nt * 8 + c4 * 2;
                const float bz0 = __ldg(bias + n0 + col);
                const float bz1 = __ldg(bias + n0 + col + 1);
                float v0 = acc[mt][nt][2 * half]     + bz0;
                float v1 = acc[mt][nt][2 * half + 1] + bz1;
                if (RELU) { v0 = fmaxf(v0, 0.f); v1 = fmaxf(v1, 0.f); }
                if (SPLIT) {
                    split2(v0, v1,
                           (__half2*)(Yhi + yrow * Cn + n0 + col),
                           (__half2*)(Ylo + yrow * Cn + n0 + col));
                } else {
                    *(float2*)(Yf + yrow * Cn + n0 + col) = make_float2(v0, v1);
                }
            }
        }
    }
}

// ---------------------------------------------------------------------------
// LayerNorm over L per (b,c), smem-staged single-pass: load slab (hi+lo for
// 400 l x 64 ch) into shared once while accumulating stats, then apply from
// shared and write once. Global traffic: 1 read + 1 write (was 2R + 1W).
// Block 256 thr = 64 channels x 4 L-strips. Grid (Bn, 4).
// torch-style: unbiased var (ddof=1), divide by (std + eps).
// ---------------------------------------------------------------------------
template <bool RELU>
__global__ __launch_bounds__(256) void ln_kernel(
    __half* __restrict__ hi, __half* __restrict__ lo,
    const float* __restrict__ g, const float* __restrict__ be) {
    extern __shared__ __align__(16) __half lsh[];   // [2][400][64]
    __half* shh = lsh;
    __half* shl = lsh + 400 * 64;
    __shared__ float red[2][4][64];
    __shared__ float stat[2][64];
    const int b = blockIdx.x, cg = blockIdx.y;
    const int cl = threadIdx.x & 63, strip = threadIdx.x >> 6;
    const size_t base = (size_t)b * Cn + cg * 64 + cl;

    float s = 0.f, q = 0.f;
    for (int l = strip; l < Ln; l += 4) {
        const size_t off = base + (size_t)l * Bn * Cn;
        const __half h = hi[off], w = lo[off];
        shh[l * 64 + cl] = h;
        shl[l * 64 + cl] = w;
        float x = __half2float(h) + __half2float(w);
        if (RELU) x = fmaxf(x, 0.f);
        s += x; q += x * x;
    }
    red[0][strip][cl] = s;
    red[1][strip][cl] = q;
    __syncthreads();
    if (threadIdx.x < 64) {
        float st = red[0][0][cl] + red[0][1][cl] + red[0][2][cl] + red[0][3][cl];
        float qt = red[1][0][cl] + red[1][1][cl] + red[1][2][cl] + red[1][3][cl];
        const float mean = st * (1.f / Ln);
        const float var = fmaxf((qt - st * mean) * (1.f / (Ln - 1)), 0.f);
        stat[0][cl] = mean;
        stat[1][cl] = 1.f / (sqrtf(var) + 1e-6f);
    }
    __syncthreads();
    const float mean = stat[0][cl], inv = stat[1][cl];
    for (int l = strip; l < Ln; l += 4) {
        const size_t off = base + (size_t)l * Bn * Cn;
        float x = __half2float(shh[l * 64 + cl]) + __half2float(shl[l * 64 + cl]);
        if (RELU) x = fmaxf(x, 0.f);
        const float y = g[l] * ((x - mean) * inv) + be[l];
        const __half h = __float2half_rn(y);
        hi[off] = h;
        lo[off] = __float2half_rn(y - __half2float(h));
    }
}

// ---------------------------------------------------------------------------
// Host orchestration
// ---------------------------------------------------------------------------
extern "C" void kernel_launch(void* const* d_in, const int* in_sizes, int n_in,
                              void* d_out, int out_size) {
    const float* E   = (const float*)d_in[0];
    const float* Wl  = (const float*)d_in[2];
    const float* bl  = (const float*)d_in[3];
    const float* w0  = (const float*)d_in[4];
    const float* b0  = (const float*)d_in[5];
    const float* w1  = (const float*)d_in[6];
    const float* b1  = (const float*)d_in[7];
    const float* w2  = (const float*)d_in[8];
    const float* b2  = (const float*)d_in[9];
    const float* g1  = (const float*)d_in[10];
    const float* be1 = (const float*)d_in[11];
    const float* g2  = (const float*)d_in[12];
    const float* be2 = (const float*)d_in[13];
    float* out = (float*)d_out;

    __half *Ah, *Al, *Bh, *Bl, *Eh, *El, *wkh, *wkl, *wlh, *wll;
    cudaGetSymbolAddress((void**)&Ah, g_Ahi);
    cudaGetSymbolAddress((void**)&Al, g_Alo);
    cudaGetSymbolAddress((void**)&Bh, g_Bhi);
    cudaGetSymbolAddress((void**)&Bl, g_Blo);
    cudaGetSymbolAddress((void**)&Eh, g_Ehi);
    cudaGetSymbolAddress((void**)&El, g_Elo);
    cudaGetSymbolAddress((void**)&wkh, g_wkhi);
    cudaGetSymbolAddress((void**)&wkl, g_wklo);
    cudaGetSymbolAddress((void**)&wlh, g_wlhi);
    cudaGetSymbolAddress((void**)&wll, g_wllo);
    __half* wk0h = wkh;               __half* wk0l = wkl;
    __half* wk1h = wkh + 3 * Cn * Cn; __half* wk1l = wkl + 3 * Cn * Cn;
    __half* wk2h = wkh + 6 * Cn * Cn; __half* wk2l = wkl + 6 * Cn * Cn;

    cudaFuncSetAttribute(mma_kernel<true, 1, false, true>,
                         cudaFuncAttributeMaxDynamicSharedMemorySize, SMEM_TOT);
    cudaFuncSetAttribute(mma_kernel<false, 1, true, true>,
                         cudaFuncAttributeMaxDynamicSharedMemorySize, SMEM_TOT);
    cudaFuncSetAttribute(mma_kernel<false, 1, false, true>,
                         cudaFuncAttributeMaxDynamicSharedMemorySize, SMEM_TOT);
    cudaFuncSetAttribute(mma_kernel<false, 2, false, true>,
                         cudaFuncAttributeMaxDynamicSharedMemorySize, SMEM_TOT);
    cudaFuncSetAttribute(mma_kernel<false, 2, false, false>,
                         cudaFuncAttributeMaxDynamicSharedMemorySize, SMEM_TOT);
    cudaFuncSetAttribute(ln_kernel<false>,
                         cudaFuncAttributeMaxDynamicSharedMemorySize, SMEM_LN);
    cudaFuncSetAttribute(ln_kernel<true>,
                         cudaFuncAttributeMaxDynamicSharedMemorySize, SMEM_LN);

    wprep_all_kernel<<<3328, 256>>>(w0, w1, w2, Wl, wkh, wkl, wlh, wll);
    esplit_kernel<<<51200, 256>>>((const float4*)E, (__half2*)Eh, (__half2*)El);

    // projection: [51200,1024] x [1024,256] -> A planes [L,B,C]
    mma_kernel<true, 1, false, true><<<800, 256, SMEM_TOT>>>(
        Eh, El, wlh, wll, bl, Ah, Al, nullptr);

    const int CG = Ln * 2;          // 400 l-tiles x 2 n-halves
    const dim3 LG(Bn, 4);

    // net 1: A -> B
    mma_kernel<false, 1, true,  true><<<CG, 256, SMEM_TOT>>>(Ah, Al, wk0h, wk0l, b0, Bh, Bl, nullptr);
    ln_kernel<false><<<LG, 256, SMEM_LN>>>(Bh, Bl, g1, be1);
    mma_kernel<false, 1, false, true><<<CG, 256, SMEM_TOT>>>(Bh, Bl, wk1h, wk1l, b1, Ah, Al, nullptr);
    mma_kernel<false, 2, false, true><<<CG, 256, SMEM_TOT>>>(Ah, Al, wk2h, wk2l, b2, Bh, Bl, nullptr);

    ln_kernel<true><<<LG, 256, SMEM_LN>>>(Bh, Bl, g2, be2);   // ReLU + outer LN

    // net 2: B -> A
    mma_kernel<false, 1, true,  true><<<CG, 256, SMEM_TOT>>>(Bh, Bl, wk0h, wk0l, b0, Ah, Al, nullptr);
    ln_kernel<false><<<LG, 256, SMEM_LN>>>(Ah, Al, g1, be1);
    mma_kernel<false, 1, false, true><<<CG, 256, SMEM_TOT>>>(Ah, Al, wk1h, wk1l, b1, Bh, Bl, nullptr);
    mma_kernel<false, 2, false, true><<<CG, 256, SMEM_TOT>>>(Bh, Bl, wk2h, wk2l, b2, Ah, Al, nullptr);

    // net 3: A -> B
    mma_kernel<false, 1, true,  true><<<CG, 256, SMEM_TOT>>>(Ah, Al, wk0h, wk0l, b0, Bh, Bl, nullptr);
    ln_kernel<false><<<LG, 256, SMEM_LN>>>(Bh, Bl, g1, be1);
    mma_kernel<false, 1, false, true><<<CG, 256, SMEM_TOT>>>(Bh, Bl, wk1h, wk1l, b1, Ah, Al, nullptr);
    mma_kernel<false, 2, false, true><<<CG, 256, SMEM_TOT>>>(Ah, Al, wk2h, wk2l, b2, Bh, Bl, nullptr);

    // net 4: B -> out (final conv writes fp32 d_out [B,L,C])
    mma_kernel<false, 1, true,  true><<<CG, 256, SMEM_TOT>>>(Bh, Bl, wk0h, wk0l, b0, Ah, Al, nullptr);
    ln_kernel<false><<<LG, 256, SMEM_LN>>>(Ah, Al, g1, be1);
    mma_kernel<false, 1, false, true><<<CG, 256, SMEM_TOT>>>(Ah, Al, wk1h, wk1l, b1, Bh, Bl, nullptr);
    mma_kernel<false, 2, false, false><<<CG, 256, SMEM_TOT>>>(Bh, Bl, wk2h, wk2l, b2, nullptr, nullptr, out);
}